// round 2
// baseline (speedup 1.0000x reference)
#include <cuda_runtime.h>

#define T_DIM 8192
#define C_DIM 2048

// Scratch (device globals — no allocation allowed)
__device__ float g_kerq[T_DIM * C_DIM];   // 64 MB
__device__ float g_kerk[T_DIM * C_DIM];   // 64 MB
__device__ float g_v[T_DIM * C_DIM];      // 64 MB
__device__ float g_kv[C_DIM * C_DIM];     // 16 MB
__device__ float g_ksum[C_DIM];
__device__ float g_den[T_DIM];
__device__ float g_part[64 * C_DIM];
__device__ float g_ot[T_DIM * C_DIM];     // 64 MB (holds O stored transposed == permuted M)

// ---------------------------------------------------------------------------
// Generic 128x128x8 SGEMM, 256 threads, 8x8 per-thread accumulator.
// TRANS_A==1: A stored [K,M] (reads A[k*M+m]); else A is [M,K].
// EPI: 0 plain, 1 qkv(feature-map split), 2 divide-by-den + transposed store,
//      3 bias add.
// ---------------------------------------------------------------------------
template <int TRANS_A, int EPI>
__global__ __launch_bounds__(256) void sgemm_k(
    const float* __restrict__ A, const float* __restrict__ B,
    float* __restrict__ C, int M, int N, int K,
    const float* __restrict__ e0, const float* __restrict__ e1,
    const float* __restrict__ e2, const float* __restrict__ e3,
    const float* __restrict__ e4,
    float* __restrict__ o1, float* __restrict__ o2)
{
    const int tid = threadIdx.x;
    const int bm = blockIdx.y * 128;
    const int bn = blockIdx.x * 128;

    __shared__ float As[8][128];
    __shared__ float Bs[8][128];

    float acc[8][8];
#pragma unroll
    for (int i = 0; i < 8; ++i)
#pragma unroll
        for (int j = 0; j < 8; ++j) acc[i][j] = 0.0f;

    const int ty = tid >> 4;          // 0..15
    const int tx = tid & 15;          // 0..15
    const int row0 = ty * 4;          // fragment rows: row0..+3 and 64+row0..+3
    const int col0 = tx * 4;

    for (int k0 = 0; k0 < K; k0 += 8) {
        // ---- load A tile into As[k][m] ----
        if (TRANS_A) {
            const int kk = tid >> 5;            // 0..7
            const int mm = (tid & 31) << 2;     // 0..124
            const float4 a4 = *(const float4*)(A + (size_t)(k0 + kk) * M + bm + mm);
            *(float4*)&As[kk][mm] = a4;
        } else {
            const int mm = tid >> 1;            // 0..127
            const int kk = (tid & 1) << 2;      // 0 or 4
            const float4 a4 = *(const float4*)(A + (size_t)(bm + mm) * K + k0 + kk);
            As[kk + 0][mm] = a4.x;
            As[kk + 1][mm] = a4.y;
            As[kk + 2][mm] = a4.z;
            As[kk + 3][mm] = a4.w;
        }
        // ---- load B tile into Bs[k][n] ----
        {
            const int kk = tid >> 5;
            const int nn = (tid & 31) << 2;
            *(float4*)&Bs[kk][nn] = *(const float4*)(B + (size_t)(k0 + kk) * N + bn + nn);
        }
        __syncthreads();

#pragma unroll
        for (int k = 0; k < 8; ++k) {
            float a[8], b[8];
            const float4 a0 = *(const float4*)&As[k][row0];
            const float4 a1 = *(const float4*)&As[k][64 + row0];
            const float4 b0 = *(const float4*)&Bs[k][col0];
            const float4 b1 = *(const float4*)&Bs[k][64 + col0];
            a[0]=a0.x; a[1]=a0.y; a[2]=a0.z; a[3]=a0.w;
            a[4]=a1.x; a[5]=a1.y; a[6]=a1.z; a[7]=a1.w;
            b[0]=b0.x; b[1]=b0.y; b[2]=b0.z; b[3]=b0.w;
            b[4]=b1.x; b[5]=b1.y; b[6]=b1.z; b[7]=b1.w;
#pragma unroll
            for (int i = 0; i < 8; ++i)
#pragma unroll
                for (int j = 0; j < 8; ++j)
                    acc[i][j] = fmaf(a[i], b[j], acc[i][j]);
        }
        __syncthreads();
    }

    // ---- epilogue ----
#pragma unroll
    for (int i = 0; i < 8; ++i) {
        const int m = bm + ((i < 4) ? (row0 + i) : (64 + row0 + i - 4));
        float rden = 1.0f;
        if (EPI == 2) rden = e0[m];   // den[t]
#pragma unroll
        for (int j = 0; j < 8; ++j) {
            const int n = bn + ((j < 4) ? (col0 + j) : (64 + col0 + j - 4));
            float val = acc[i][j];
            if (EPI == 0) {
                C[(size_t)m * N + n] = val;
            } else if (EPI == 1) {
                val += e0[n];  // b_attn
                if (n < C_DIM) {
                    const float t = fmaf(e1[n], val, e2[n]);          // gamma_q, beta_q
                    C[(size_t)m * C_DIM + n] = t * t;                 // kerq
                } else if (n < 2 * C_DIM) {
                    const int nn = n - C_DIM;
                    const float t = fmaf(e3[nn], val, e4[nn]);        // gamma_k, beta_k
                    o1[(size_t)m * C_DIM + nn] = t * t;               // kerk
                } else {
                    o2[(size_t)m * C_DIM + (n - 2 * C_DIM)] = val;    // v
                }
            } else if (EPI == 2) {
                // O[m][n] / den[m], stored transposed: flat index n*M + m.
                // Read back row-major [T,C] this IS the permuted matrix M.
                C[(size_t)n * M + m] = val / rden;
            } else {
                C[(size_t)m * N + n] = val + e0[n];                   // + b_out
            }
        }
    }
}

// ---------------------------------------------------------------------------
// ksum = column sums of kerk (deterministic two-phase)
// ---------------------------------------------------------------------------
__global__ void colsum_part(const float* __restrict__ kerk, float* __restrict__ part) {
    const int col = blockIdx.x * 256 + threadIdx.x;   // gridDim.x = 8
    const int rc = blockIdx.y;                        // 64 row chunks of 128
    const int t0 = rc * 128;
    float s = 0.0f;
    for (int t = 0; t < 128; ++t) s += kerk[(size_t)(t0 + t) * C_DIM + col];
    part[rc * C_DIM + col] = s;
}

__global__ void colsum_reduce(const float* __restrict__ part, float* __restrict__ ksum) {
    const int col = blockIdx.x * 256 + threadIdx.x;
    float s = 0.0f;
    for (int r = 0; r < 64; ++r) s += part[r * C_DIM + col];
    ksum[col] = s;
}

// ---------------------------------------------------------------------------
// den[t] = kerq[t,:] . ksum  (one warp per row)
// ---------------------------------------------------------------------------
__global__ void den_kernel(const float* __restrict__ kerq,
                           const float* __restrict__ ksum,
                           float* __restrict__ den) {
    const int warp = (blockIdx.x * blockDim.x + threadIdx.x) >> 5;
    const int lane = threadIdx.x & 31;
    if (warp >= T_DIM) return;
    const float* row = kerq + (size_t)warp * C_DIM;
    float s = 0.0f;
    for (int c = lane; c < C_DIM; c += 32) s = fmaf(row[c], ksum[c], s);
#pragma unroll
    for (int o = 16; o; o >>= 1) s += __shfl_xor_sync(0xffffffffu, s, o);
    if (lane == 0) den[warp] = s;
}

// ---------------------------------------------------------------------------
extern "C" void kernel_launch(void* const* d_in, const int* in_sizes, int n_in,
                              void* d_out, int out_size)
{
    const float* x      = (const float*)d_in[0];
    const float* w_attn = (const float*)d_in[1];
    const float* b_attn = (const float*)d_in[2];
    const float* gq     = (const float*)d_in[3];
    const float* bq     = (const float*)d_in[4];
    const float* gk     = (const float*)d_in[5];
    const float* bk     = (const float*)d_in[6];
    const float* w_out  = (const float*)d_in[7];
    const float* b_out  = (const float*)d_in[8];
    float* out = (float*)d_out;

    float *kerq, *kerk, *v, *kv, *ksum, *den, *part, *ot;
    cudaGetSymbolAddress((void**)&kerq, g_kerq);
    cudaGetSymbolAddress((void**)&kerk, g_kerk);
    cudaGetSymbolAddress((void**)&v,    g_v);
    cudaGetSymbolAddress((void**)&kv,   g_kv);
    cudaGetSymbolAddress((void**)&ksum, g_ksum);
    cudaGetSymbolAddress((void**)&den,  g_den);
    cudaGetSymbolAddress((void**)&part, g_part);
    cudaGetSymbolAddress((void**)&ot,   g_ot);

    const dim3 blk(256);

    // G1: qkv = x @ w_attn + b_attn, fused feature maps -> kerq, kerk, v
    sgemm_k<0, 1><<<dim3(3 * C_DIM / 128, T_DIM / 128), blk>>>(
        x, w_attn, kerq, T_DIM, 3 * C_DIM, C_DIM,
        b_attn, gq, bq, gk, bk, kerk, v);

    // G2: kv = kerk^T @ v   [C,C], K = T
    sgemm_k<1, 0><<<dim3(C_DIM / 128, C_DIM / 128), blk>>>(
        kerk, v, kv, C_DIM, C_DIM, T_DIM,
        nullptr, nullptr, nullptr, nullptr, nullptr, nullptr, nullptr);

    // ksum = column sums of kerk (two-phase, deterministic)
    colsum_part<<<dim3(C_DIM / 256, 64), blk>>>(kerk, part);
    colsum_reduce<<<C_DIM / 256, blk>>>(part, ksum);

    // den[t] = kerq[t,:] . ksum
    den_kernel<<<T_DIM / 8, blk>>>(kerq, ksum, den);

    // G3: O = (kerq @ kv) / den, stored transposed into ot (== permuted M)
    sgemm_k<0, 2><<<dim3(C_DIM / 128, T_DIM / 128), blk>>>(
        kerq, kv, ot, T_DIM, C_DIM, C_DIM,
        den, nullptr, nullptr, nullptr, nullptr, nullptr, nullptr);

    // G4: out = M @ w_out + b_out
    sgemm_k<0, 3><<<dim3(C_DIM / 128, T_DIM / 128), blk>>>(
        ot, w_out, out, T_DIM, C_DIM, C_DIM,
        b_out, nullptr, nullptr, nullptr, nullptr, nullptr, nullptr);
}

// round 7
// speedup vs baseline: 2.4064x; 2.4064x over previous
#include <cuda_runtime.h>
#include <cuda_bf16.h>
#include <cstdint>

#define T_DIM 8192
#define C_DIM 2048

// ---------------- scratch (device globals; no allocation allowed) ----------
__device__ __align__(128) __nv_bfloat16 g_xh [T_DIM * C_DIM];
__device__ __align__(128) __nv_bfloat16 g_xl [T_DIM * C_DIM];
__device__ __align__(128) __nv_bfloat16 g_wTh[3 * C_DIM * C_DIM];
__device__ __align__(128) __nv_bfloat16 g_wTl[3 * C_DIM * C_DIM];
__device__ __align__(128) __nv_bfloat16 g_woTh[C_DIM * C_DIM];
__device__ __align__(128) __nv_bfloat16 g_woTl[C_DIM * C_DIM];
__device__ __align__(128) __nv_bfloat16 g_kqh[T_DIM * C_DIM];   // kerq [T,C]
__device__ __align__(128) __nv_bfloat16 g_kql[T_DIM * C_DIM];
__device__ __align__(128) __nv_bfloat16 g_kkTh[C_DIM * T_DIM];  // kerk^T [C,T]
__device__ __align__(128) __nv_bfloat16 g_kkTl[C_DIM * T_DIM];
__device__ __align__(128) __nv_bfloat16 g_vTh[C_DIM * T_DIM];   // v^T [C,T]
__device__ __align__(128) __nv_bfloat16 g_vTl[C_DIM * T_DIM];
__device__ __align__(128) __nv_bfloat16 g_kvTh[C_DIM * C_DIM];  // kv^T [d,c]
__device__ __align__(128) __nv_bfloat16 g_kvTl[C_DIM * C_DIM];
__device__ __align__(128) __nv_bfloat16 g_oth[C_DIM * T_DIM];   // ot flat (== permuted M read [T,C])
__device__ __align__(128) __nv_bfloat16 g_otl[C_DIM * T_DIM];
__device__ float g_ksum[C_DIM];
__device__ float g_den[T_DIM];

#define SW128(o) ((o) ^ (((o) >> 3) & 0x70))

__device__ __forceinline__ uint32_t smem_u32(const void* p) {
    uint32_t a;
    asm("{ .reg .u64 t; cvta.to.shared.u64 t, %1; cvt.u32.u64 %0, t; }" : "=r"(a) : "l"(p));
    return a;
}

__device__ __forceinline__ void ldsm4(uint32_t* r, uint32_t addr) {
    asm volatile("ldmatrix.sync.aligned.m8n8.x4.shared.b16 {%0,%1,%2,%3}, [%4];"
        : "=r"(r[0]), "=r"(r[1]), "=r"(r[2]), "=r"(r[3]) : "r"(addr));
}

__device__ __forceinline__ void mma16816(float* c, const uint32_t* a,
                                         uint32_t b0, uint32_t b1) {
    asm volatile("mma.sync.aligned.m16n8k16.row.col.f32.bf16.bf16.f32 "
        "{%0,%1,%2,%3}, {%4,%5,%6,%7}, {%8,%9}, {%0,%1,%2,%3};"
        : "+f"(c[0]), "+f"(c[1]), "+f"(c[2]), "+f"(c[3])
        : "r"(a[0]), "r"(a[1]), "r"(a[2]), "r"(a[3]), "r"(b0), "r"(b1));
}

__device__ __forceinline__ void split2(float v, __nv_bfloat16& h, __nv_bfloat16& l) {
    h = __float2bfloat16_rn(v);
    l = __float2bfloat16_rn(v - __bfloat162float(h));
}

// ---------------- cp.async chunk loader: 4 tiles (Ah,Al,Bh,Bl) 128x64bf16 ---
__device__ __forceinline__ void load_chunk(
    uint32_t s0, int stage,
    const char* gAh, const char* gAl, const char* gBh, const char* gBl,
    int ldb, int k0b, int tid)
{
    const char* gb[4] = {gAh, gAl, gBh, gBl};
    const uint32_t sb = s0 + stage * 65536;
#pragma unroll
    for (int t4 = 0; t4 < 4; ++t4) {
#pragma unroll
        for (int r = 0; r < 4; ++r) {
            const int seg = tid + r * 256;
            const int row = seg >> 3;
            const int so  = (seg & 7) * 16;
            const char* g = gb[t4] + (size_t)row * ldb + k0b + so;
            const uint32_t s = sb + t4 * 16384 + SW128(row * 128 + so);
            asm volatile("cp.async.cg.shared.global [%0], [%1], 16;\n" :: "r"(s), "l"(g));
        }
    }
}

// ---------------- mma.sync split GEMM ---------------------------------------
// D[M,N] = (Ah+Al)[M,K] @ (Bh+Bl)[N,K]^T   (3-pass hi/lo, fp32 accum in regs)
// Tiles 128x128, BK=64, 3 cp.async stages. 8 warps (2x4), warp tile 64x32.
// EPI: 1=G1 (qkv feature maps), 2=G2 (kvT), 3=G3 (/den + ot), 4=G4 (bias+out)
template <int EPI>
__global__ void __launch_bounds__(256) mm_k(
    const __nv_bfloat16* __restrict__ Ah, const __nv_bfloat16* __restrict__ Al,
    const __nv_bfloat16* __restrict__ Bh, const __nv_bfloat16* __restrict__ Bl,
    int K,
    const float* __restrict__ f0, const float* __restrict__ f1,
    const float* __restrict__ f2, const float* __restrict__ f3,
    const float* __restrict__ f4,
    __nv_bfloat16* __restrict__ o0, __nv_bfloat16* __restrict__ o1,
    __nv_bfloat16* __restrict__ o2, __nv_bfloat16* __restrict__ o3,
    __nv_bfloat16* __restrict__ o4, __nv_bfloat16* __restrict__ o5,
    float* __restrict__ fout)
{
    extern __shared__ char smem[];
    const uint32_t s0 = smem_u32(smem);
    const int tid = threadIdx.x;
    const int wid = tid >> 5, lane = tid & 31;
    const int bm = blockIdx.y * 128;
    const int bn = blockIdx.x * 128;

    const int ldb = K * 2;
    const char* gAh = (const char*)Ah + (size_t)bm * ldb;
    const char* gAl = (const char*)Al + (size_t)bm * ldb;
    const char* gBh = (const char*)Bh + (size_t)bn * ldb;
    const char* gBl = (const char*)Bl + (size_t)bn * ldb;
    const int nchunk = K >> 6;

    float acc[4][4][4];
#pragma unroll
    for (int a = 0; a < 4; ++a)
#pragma unroll
        for (int b = 0; b < 4; ++b)
#pragma unroll
            for (int c = 0; c < 4; ++c) acc[a][b][c] = 0.0f;

    const int wm = (wid & 1) * 64;          // warp M offset
    const int wn = (wid >> 1) * 32;         // warp N offset
    const int lr = lane & 15;               // ldmatrix row-within-16
    const int lc = (lane >> 4) * 16;        // ldmatrix k-halve byte sel

    // prologue: stages 0,1
    for (int c = 0; c < 2 && c < nchunk; ++c) {
        load_chunk(s0, c, gAh, gAl, gBh, gBl, ldb, c * 128, tid);
        asm volatile("cp.async.commit_group;" ::: "memory");
    }

    for (int i = 0; i < nchunk; ++i) {
        if (i + 1 < nchunk) asm volatile("cp.async.wait_group 1;" ::: "memory");
        else                asm volatile("cp.async.wait_group 0;" ::: "memory");
        __syncthreads();

        const int j = i + 2;
        if (j < nchunk) {
            load_chunk(s0, j % 3, gAh, gAl, gBh, gBl, ldb, j * 128, tid);
            asm volatile("cp.async.commit_group;" ::: "memory");
        }

        const uint32_t sb  = s0 + (i % 3) * 65536;
        const uint32_t aHb = sb, aLb = sb + 16384, bHb = sb + 32768, bLb = sb + 49152;

#pragma unroll
        for (int kk = 0; kk < 4; ++kk) {
            const int kb = kk * 32;
            uint32_t ah[4][4], al[4][4], bh[2][4], bl[2][4];
#pragma unroll
            for (int mf = 0; mf < 4; ++mf) {
                const uint32_t off = SW128((wm + mf * 16 + lr) * 128 + kb + lc);
                ldsm4(ah[mf], aHb + off);
                ldsm4(al[mf], aLb + off);
            }
#pragma unroll
            for (int nf2 = 0; nf2 < 2; ++nf2) {
                const uint32_t off = SW128((wn + nf2 * 16 + lr) * 128 + kb + lc);
                ldsm4(bh[nf2], bHb + off);
                ldsm4(bl[nf2], bLb + off);
            }
#pragma unroll
            for (int mf = 0; mf < 4; ++mf)
#pragma unroll
                for (int nf = 0; nf < 4; ++nf) {
                    const int n2 = nf >> 1, sub = nf & 1;
                    mma16816(acc[mf][nf], ah[mf], bh[n2][sub], bh[n2][2 + sub]);
                    mma16816(acc[mf][nf], ah[mf], bl[n2][sub], bl[n2][2 + sub]);
                    mma16816(acc[mf][nf], al[mf], bh[n2][sub], bh[n2][2 + sub]);
                }
        }
    }

    // ---------------- epilogue (fragment layout: rows l/4, l/4+8; cols 2(l%4)+{0,1})
#pragma unroll
    for (int mf = 0; mf < 4; ++mf) {
        const int m0 = bm + wm + mf * 16 + (lane >> 2);
        const int m1 = m0 + 8;
        float rd0 = 1.0f, rd1 = 1.0f;
        if (EPI == 3) { rd0 = 1.0f / f0[m0]; rd1 = 1.0f / f0[m1]; }
#pragma unroll
        for (int nf = 0; nf < 4; ++nf) {
            const int n0 = bn + wn + nf * 8 + 2 * (lane & 3);
            const int n1 = n0 + 1;
            const float* a4 = acc[mf][nf];

            if (EPI == 1) {
                const int region = bn >> 11;  // uniform per block: 0=q 1=k 2=v
                if (region == 0) {
                    const float b0v = f0[n0], b1v = f0[n1];
                    const float g0 = f1[n0], g1 = f1[n1], e0 = f2[n0], e1 = f2[n1];
#pragma unroll
                    for (int h = 0; h < 2; ++h) {
                        const int m = h ? m1 : m0;
                        const float t0 = fmaf(g0, a4[2 * h + 0] + b0v, e0);
                        const float t1 = fmaf(g1, a4[2 * h + 1] + b1v, e1);
                        __nv_bfloat16 h0, l0, h1, l1;
                        split2(t0 * t0, h0, l0);  split2(t1 * t1, h1, l1);
                        const size_t o = (size_t)m * C_DIM + n0;
                        *(__nv_bfloat162*)(o0 + o) = __nv_bfloat162{h0, h1};
                        *(__nv_bfloat162*)(o1 + o) = __nv_bfloat162{l0, l1};
                    }
                } else if (region == 1) {
                    const int nn0 = n0 - C_DIM, nn1 = n1 - C_DIM;
                    const float b0v = f0[n0], b1v = f0[n1];
                    const float g0 = f3[nn0], g1 = f3[nn1], e0 = f4[nn0], e1 = f4[nn1];
#pragma unroll
                    for (int h = 0; h < 2; ++h) {
                        const int m = h ? m1 : m0;
                        const float t0 = fmaf(g0, a4[2 * h + 0] + b0v, e0);
                        const float t1 = fmaf(g1, a4[2 * h + 1] + b1v, e1);
                        __nv_bfloat16 h0, l0, h1, l1;
                        split2(t0 * t0, h0, l0);  split2(t1 * t1, h1, l1);
                        o2[(size_t)nn0 * T_DIM + m] = h0;  o3[(size_t)nn0 * T_DIM + m] = l0;
                        o2[(size_t)nn1 * T_DIM + m] = h1;  o3[(size_t)nn1 * T_DIM + m] = l1;
                    }
                } else {
                    const int nn0 = n0 - 2 * C_DIM, nn1 = n1 - 2 * C_DIM;
                    const float b0v = f0[n0], b1v = f0[n1];
#pragma unroll
                    for (int h = 0; h < 2; ++h) {
                        const int m = h ? m1 : m0;
                        __nv_bfloat16 h0, l0, h1, l1;
                        split2(a4[2 * h + 0] + b0v, h0, l0);
                        split2(a4[2 * h + 1] + b1v, h1, l1);
                        o4[(size_t)nn0 * T_DIM + m] = h0;  o5[(size_t)nn0 * T_DIM + m] = l0;
                        o4[(size_t)nn1 * T_DIM + m] = h1;  o5[(size_t)nn1 * T_DIM + m] = l1;
                    }
                }
            } else if (EPI == 2) {
#pragma unroll
                for (int h = 0; h < 2; ++h) {
                    const int m = h ? m1 : m0;
                    __nv_bfloat16 h0, l0, h1, l1;
                    split2(a4[2 * h + 0], h0, l0);
                    split2(a4[2 * h + 1], h1, l1);
                    o0[(size_t)n0 * C_DIM + m] = h0;  o1[(size_t)n0 * C_DIM + m] = l0;
                    o0[(size_t)n1 * C_DIM + m] = h1;  o1[(size_t)n1 * C_DIM + m] = l1;
                }
            } else if (EPI == 3) {
#pragma unroll
                for (int h = 0; h < 2; ++h) {
                    const int m = h ? m1 : m0;
                    const float rd = h ? rd1 : rd0;
                    __nv_bfloat16 h0, l0, h1, l1;
                    split2(a4[2 * h + 0] * rd, h0, l0);
                    split2(a4[2 * h + 1] * rd, h1, l1);
                    o0[(size_t)n0 * T_DIM + m] = h0;  o1[(size_t)n0 * T_DIM + m] = l0;
                    o0[(size_t)n1 * T_DIM + m] = h1;  o1[(size_t)n1 * T_DIM + m] = l1;
                }
            } else {  // EPI 4: + b_out, natural fp32 store
                const float b0v = f0[n0], b1v = f0[n1];
#pragma unroll
                for (int h = 0; h < 2; ++h) {
                    const int m = h ? m1 : m0;
                    float2 v2 = make_float2(a4[2 * h + 0] + b0v, a4[2 * h + 1] + b1v);
                    *(float2*)(fout + (size_t)m * C_DIM + n0) = v2;
                }
            }
        }
    }
}

// ---------------- conversion / reduction kernels ----------------------------
__global__ void split_k(const float* __restrict__ in, __nv_bfloat16* __restrict__ oh,
                        __nv_bfloat16* __restrict__ ol, int n) {
    const int i = blockIdx.x * 256 + threadIdx.x;
    if (i < n) {
        __nv_bfloat16 h, l;  split2(in[i], h, l);
        oh[i] = h;  ol[i] = l;
    }
}

__global__ void splitT_k(const float* __restrict__ in, __nv_bfloat16* __restrict__ oh,
                         __nv_bfloat16* __restrict__ ol, int R, int Cc) {
    __shared__ float t[32][33];
    const int c0 = blockIdx.x * 32, r0 = blockIdx.y * 32;
    for (int i = threadIdx.y; i < 32; i += 8)
        t[i][threadIdx.x] = in[(size_t)(r0 + i) * Cc + c0 + threadIdx.x];
    __syncthreads();
    for (int i = threadIdx.y; i < 32; i += 8) {
        const float v = t[threadIdx.x][i];
        __nv_bfloat16 h, l;  split2(v, h, l);
        const size_t o = (size_t)(c0 + i) * R + r0 + threadIdx.x;
        oh[o] = h;  ol[o] = l;
    }
}

__global__ void ksum_k(const __nv_bfloat16* __restrict__ kh,
                       const __nv_bfloat16* __restrict__ kl, float* __restrict__ out) {
    __shared__ float red[256];
    const int c = blockIdx.x;
    const __nv_bfloat16* ph = kh + (size_t)c * T_DIM;
    const __nv_bfloat16* pl = kl + (size_t)c * T_DIM;
    float s = 0.0f;
    for (int t = threadIdx.x; t < T_DIM; t += 256)
        s += __bfloat162float(ph[t]) + __bfloat162float(pl[t]);
    red[threadIdx.x] = s;  __syncthreads();
    for (int o = 128; o; o >>= 1) {
        if (threadIdx.x < o) red[threadIdx.x] += red[threadIdx.x + o];
        __syncthreads();
    }
    if (threadIdx.x == 0) out[c] = red[0];
}

__global__ void den_k(const __nv_bfloat16* __restrict__ qh, const __nv_bfloat16* __restrict__ ql,
                      const float* __restrict__ ks, float* __restrict__ den) {
    const int w = (blockIdx.x * blockDim.x + threadIdx.x) >> 5;
    const int l = threadIdx.x & 31;
    if (w >= T_DIM) return;
    const __nv_bfloat16* ph = qh + (size_t)w * C_DIM;
    const __nv_bfloat16* pl = ql + (size_t)w * C_DIM;
    float s = 0.0f;
    for (int c = l; c < C_DIM; c += 32)
        s = fmaf(__bfloat162float(ph[c]) + __bfloat162float(pl[c]), ks[c], s);
#pragma unroll
    for (int o = 16; o; o >>= 1) s += __shfl_xor_sync(0xffffffffu, s, o);
    if (l == 0) den[w] = s;
}

// ---------------- launch -----------------------------------------------------
extern "C" void kernel_launch(void* const* d_in, const int* in_sizes, int n_in,
                              void* d_out, int out_size)
{
    const float* x      = (const float*)d_in[0];
    const float* w_attn = (const float*)d_in[1];
    const float* b_attn = (const float*)d_in[2];
    const float* gq     = (const float*)d_in[3];
    const float* bq     = (const float*)d_in[4];
    const float* gk     = (const float*)d_in[5];
    const float* bk     = (const float*)d_in[6];
    const float* w_out  = (const float*)d_in[7];
    const float* b_out  = (const float*)d_in[8];
    float* out = (float*)d_out;

    __nv_bfloat16 *xh, *xl, *wTh, *wTl, *woTh, *woTl, *kqh, *kql,
                  *kkTh, *kkTl, *vTh, *vTl, *kvTh, *kvTl, *oth, *otl;
    float *ksum, *den;
    cudaGetSymbolAddress((void**)&xh, g_xh);     cudaGetSymbolAddress((void**)&xl, g_xl);
    cudaGetSymbolAddress((void**)&wTh, g_wTh);   cudaGetSymbolAddress((void**)&wTl, g_wTl);
    cudaGetSymbolAddress((void**)&woTh, g_woTh); cudaGetSymbolAddress((void**)&woTl, g_woTl);
    cudaGetSymbolAddress((void**)&kqh, g_kqh);   cudaGetSymbolAddress((void**)&kql, g_kql);
    cudaGetSymbolAddress((void**)&kkTh, g_kkTh); cudaGetSymbolAddress((void**)&kkTl, g_kkTl);
    cudaGetSymbolAddress((void**)&vTh, g_vTh);   cudaGetSymbolAddress((void**)&vTl, g_vTl);
    cudaGetSymbolAddress((void**)&kvTh, g_kvTh); cudaGetSymbolAddress((void**)&kvTl, g_kvTl);
    cudaGetSymbolAddress((void**)&oth, g_oth);   cudaGetSymbolAddress((void**)&otl, g_otl);
    cudaGetSymbolAddress((void**)&ksum, g_ksum); cudaGetSymbolAddress((void**)&den, g_den);

    const int SMEM_BYTES = 3 * 65536;  // 192 KB: 3 stages x (Ah,Al,Bh,Bl 16KB each)
    cudaFuncSetAttribute((const void*)mm_k<1>, cudaFuncAttributeMaxDynamicSharedMemorySize, SMEM_BYTES);
    cudaFuncSetAttribute((const void*)mm_k<2>, cudaFuncAttributeMaxDynamicSharedMemorySize, SMEM_BYTES);
    cudaFuncSetAttribute((const void*)mm_k<3>, cudaFuncAttributeMaxDynamicSharedMemorySize, SMEM_BYTES);
    cudaFuncSetAttribute((const void*)mm_k<4>, cudaFuncAttributeMaxDynamicSharedMemorySize, SMEM_BYTES);

    // conversions
    split_k<<<(T_DIM * C_DIM) / 256, 256>>>(x, xh, xl, T_DIM * C_DIM);
    splitT_k<<<dim3(3 * C_DIM / 32, C_DIM / 32), dim3(32, 8)>>>(w_attn, wTh, wTl, C_DIM, 3 * C_DIM);
    splitT_k<<<dim3(C_DIM / 32, C_DIM / 32), dim3(32, 8)>>>(w_out, woTh, woTl, C_DIM, C_DIM);

    // G1: qkv + feature maps -> kerq (natural), kerkT, vT
    mm_k<1><<<dim3(3 * C_DIM / 128, T_DIM / 128), 256, SMEM_BYTES>>>(
        xh, xl, wTh, wTl, C_DIM,
        b_attn, gq, bq, gk, bk,
        kqh, kql, kkTh, kkTl, vTh, vTl, nullptr);

    // ksum, den
    ksum_k<<<C_DIM, 256>>>(kkTh, kkTl, ksum);
    den_k<<<T_DIM * 32 / 256, 256>>>(kqh, kql, ksum, den);

    // G2: kv^T  (D[c,d] stored transposed -> kvT[d,c])
    mm_k<2><<<dim3(C_DIM / 128, C_DIM / 128), 256, SMEM_BYTES>>>(
        kkTh, kkTl, vTh, vTl, T_DIM,
        nullptr, nullptr, nullptr, nullptr, nullptr,
        kvTh, kvTl, nullptr, nullptr, nullptr, nullptr, nullptr);

    // G3: num/den, transposed store -> ot (== permuted M read as [T,C])
    mm_k<3><<<dim3(C_DIM / 128, T_DIM / 128), 256, SMEM_BYTES>>>(
        kqh, kql, kvTh, kvTl, C_DIM,
        den, nullptr, nullptr, nullptr, nullptr,
        oth, otl, nullptr, nullptr, nullptr, nullptr, nullptr);

    // G4: out = M @ w_out + b_out
    mm_k<4><<<dim3(C_DIM / 128, T_DIM / 128), 256, SMEM_BYTES>>>(
        oth, otl, woTh, woTl, C_DIM,
        b_out, nullptr, nullptr, nullptr, nullptr,
        nullptr, nullptr, nullptr, nullptr, nullptr, nullptr, out);
}